// round 8
// baseline (speedup 1.0000x reference)
#include <cuda_runtime.h>
#include <cstdint>

// ---------------------------------------------------------------------------
// StandGCN2: 2-layer GCN. N<=100096, F=128 -> 128 -> 64.
//   dinv = rsqrt(1+indeg)
//   hs1  = dinv[r]*(x @ W1)                  (GEMM1, f32x2 packed FMA)
//   CSR: edges counting-sorted by dst -> rowptr + esrc (src list per node)
//   fused: agg[r] = hs1[r] + sum hs1[esrc]; A = relu(dinv*agg+b1);
//          hs2 = dinv[r]*(A @ W2)            (one kernel, reg aggregation)
//   OUT[d] = dinv[d]*(hs2[d] + sum hs2[esrc]) + b2   (CSR, fused epilogue)
// ---------------------------------------------------------------------------

#define MAXN 100096
#define MAXE 1200000

__device__ int g_cnt[MAXN];        // in-degree (no self loop)
__device__ int g_rowptr[MAXN + 1];
__device__ int g_cur[MAXN];
__device__ int g_esrc[MAXE];
__device__ float g_dinv[MAXN];
__device__ __align__(16) float g_hs1[(size_t)MAXN * 128];
__device__ __align__(16) float g_hs2[(size_t)MAXN * 64];

typedef unsigned long long u64;

#define FMA2(d, a, b) \
    asm("fma.rn.f32x2 %0, %1, %2, %3;" : "=l"(d) : "l"(a), "l"(b), "l"(d))
#define DUP2(d, x) \
    asm("mov.b64 %0, {%1, %1};" : "=l"(d) : "r"(__float_as_uint(x)))

__device__ __forceinline__ float2 u64_as_f2(u64 v) {
    float2 r;
    asm("mov.b64 {%0, %1}, %2;" : "=f"(r.x), "=f"(r.y) : "l"(v));
    return r;
}

// ---------------------------------------------------------------------------
// Preprocessing: histogram -> scan(+dinv) -> counting sort (CSR)
// ---------------------------------------------------------------------------
__global__ void k_init(int n) {
    int i = blockIdx.x * blockDim.x + threadIdx.x;
    if (i < n) g_cnt[i] = 0;
}

__global__ void k_count(const int* __restrict__ dst, int e) {
    int i = blockIdx.x * blockDim.x + threadIdx.x;
    if (i < e) atomicAdd(&g_cnt[dst[i]], 1);
}

// Single block, 1024 threads, ~98 nodes/thread; warp-shuffle scan.
// Writes rowptr (exclusive), cur (= rowptr), dinv = rsqrt(1+cnt).
__global__ void k_scan(int n) {
    __shared__ int wsum[32];
    const int t = threadIdx.x;
    const int per = (n + 1023) / 1024;
    const int base = t * per;

    int s = 0;
    for (int i = 0; i < per; i++) {
        int idx = base + i;
        if (idx < n) s += g_cnt[idx];
    }
    const int lane = t & 31, w = t >> 5;
    int ps = s;
#pragma unroll
    for (int o = 1; o < 32; o <<= 1) {
        int y = __shfl_up_sync(0xFFFFFFFFu, ps, o);
        if (lane >= o) ps += y;
    }
    if (lane == 31) wsum[w] = ps;
    __syncthreads();
    if (w == 0) {
        int ws = wsum[lane];
#pragma unroll
        for (int o = 1; o < 32; o <<= 1) {
            int y = __shfl_up_sync(0xFFFFFFFFu, ws, o);
            if (lane >= o) ws += y;
        }
        wsum[lane] = ws;
    }
    __syncthreads();
    int run = ps - s + (w > 0 ? wsum[w - 1] : 0);
    for (int i = 0; i < per; i++) {
        int idx = base + i;
        if (idx < n) {
            int c = g_cnt[idx];
            g_rowptr[idx] = run;
            g_cur[idx] = run;
            g_dinv[idx] = rsqrtf((float)(1 + c));
            run += c;
        }
    }
    if (t == 1023) g_rowptr[n] = run;
}

__global__ void k_sort(const int* __restrict__ src, const int* __restrict__ dst,
                       int e) {
    int i = blockIdx.x * blockDim.x + threadIdx.x;
    if (i >= e) return;
    int pos = atomicAdd(&g_cur[dst[i]], 1);
    g_esrc[pos] = src[i];
}

// ---------------------------------------------------------------------------
// GEMM1: hs1 = dinv[r] * (X @ W1),  X:[M,128], W1:[128,128]
// Block 128x128, 256 threads, 8x8 microtile via f32x2, double-buffered.
// ---------------------------------------------------------------------------
__global__ __launch_bounds__(256, 2) void k_gemm1(const float* __restrict__ X,
                                                  const float* __restrict__ W,
                                                  int M) {
    __shared__ float As[2][16][128];
    __shared__ float Bs[2][16][128];

    const int tid = threadIdx.x;
    const int row0 = blockIdx.x * 128;
    const int tx = tid & 15, ty = tid >> 4;
    const int r0 = ty * 8, c0 = tx * 8;

    u64 acc[4][8];
#pragma unroll
    for (int i = 0; i < 4; i++)
#pragma unroll
        for (int j = 0; j < 8; j++) acc[i][j] = 0ull;

    float4 ra[2], rb[2];

    auto ldg = [&](int kc) {
#pragma unroll
        for (int l = 0; l < 2; l++) {
            int i = tid + l * 256;
            int r = i & 127, q4 = i >> 7;
            int gr = row0 + r;
            ra[l] = make_float4(0.f, 0.f, 0.f, 0.f);
            if (gr < M)
                ra[l] = reinterpret_cast<const float4*>(X)[(size_t)gr * 32 + kc * 4 + q4];
            rb[l] = reinterpret_cast<const float4*>(W)[(size_t)kc * 512 + i];
        }
    };
    auto sts = [&](int buf) {
#pragma unroll
        for (int l = 0; l < 2; l++) {
            int i = tid + l * 256;
            int r = i & 127, q4 = i >> 7;
            As[buf][q4 * 4 + 0][r] = ra[l].x;
            As[buf][q4 * 4 + 1][r] = ra[l].y;
            As[buf][q4 * 4 + 2][r] = ra[l].z;
            As[buf][q4 * 4 + 3][r] = ra[l].w;
            reinterpret_cast<float4*>(&Bs[buf][0][0])[i] = rb[l];
        }
    };

    ldg(0);
    sts(0);
    ldg(1);
    __syncthreads();

    for (int kc = 0; kc < 8; kc++) {
        const int cur = kc & 1;
        if (kc + 1 < 8) sts((kc + 1) & 1);
        if (kc + 2 < 8) ldg(kc + 2);
#pragma unroll
        for (int k = 0; k < 16; k++) {
            ulonglong2 a01 = *reinterpret_cast<const ulonglong2*>(&As[cur][k][r0]);
            ulonglong2 a23 = *reinterpret_cast<const ulonglong2*>(&As[cur][k][r0 + 4]);
            float4 bl = *reinterpret_cast<const float4*>(&Bs[cur][k][c0]);
            float4 bh = *reinterpret_cast<const float4*>(&Bs[cur][k][c0 + 4]);
            u64 ap[4] = {a01.x, a01.y, a23.x, a23.y};
            u64 bb[8];
            DUP2(bb[0], bl.x); DUP2(bb[1], bl.y); DUP2(bb[2], bl.z); DUP2(bb[3], bl.w);
            DUP2(bb[4], bh.x); DUP2(bb[5], bh.y); DUP2(bb[6], bh.z); DUP2(bb[7], bh.w);
#pragma unroll
            for (int rp = 0; rp < 4; rp++)
#pragma unroll
                for (int j = 0; j < 8; j++) FMA2(acc[rp][j], ap[rp], bb[j]);
        }
        __syncthreads();
    }

#pragma unroll
    for (int rp = 0; rp < 4; rp++) {
        int gre = row0 + r0 + 2 * rp;
        float2 p[8];
#pragma unroll
        for (int j = 0; j < 8; j++) p[j] = u64_as_f2(acc[rp][j]);
#pragma unroll
        for (int h = 0; h < 2; h++) {
            int gr = gre + h;
            if (gr >= M) break;
            float dv = g_dinv[gr];
            float4 v0, v1;
            if (h == 0) {
                v0 = make_float4(p[0].x, p[1].x, p[2].x, p[3].x);
                v1 = make_float4(p[4].x, p[5].x, p[6].x, p[7].x);
            } else {
                v0 = make_float4(p[0].y, p[1].y, p[2].y, p[3].y);
                v1 = make_float4(p[4].y, p[5].y, p[6].y, p[7].y);
            }
            v0.x *= dv; v0.y *= dv; v0.z *= dv; v0.w *= dv;
            v1.x *= dv; v1.y *= dv; v1.z *= dv; v1.w *= dv;
            *reinterpret_cast<float4*>(&g_hs1[(size_t)gr * 128 + c0]) = v0;
            *reinterpret_cast<float4*>(&g_hs1[(size_t)gr * 128 + c0 + 4]) = v1;
        }
    }
}

// ---------------------------------------------------------------------------
// Fused layer-2: per 64-row block,
//   phase 1 (CSR agg, registers): acc = hs1[node] + sum hs1[esrc];
//                                 As[r][:] = relu(dinv*acc + b1)
//   phase 2 (GEMM 64x64x128):     hs2 = dinv[r] * (As @ W2)
// ---------------------------------------------------------------------------
__global__ __launch_bounds__(256) void k_fused2(const float* __restrict__ W2,
                                                const float* __restrict__ B1,
                                                int M) {
    __shared__ float As[64][132];
    __shared__ float Bs[32][64];

    const int tid = threadIdx.x;
    const int row0 = blockIdx.x * 64;
    const int w = tid >> 5, lane = tid & 31;
    const int l4 = lane * 4;

    // ---- phase 1: aggregation, warp w owns rows w*8 .. w*8+7 ----
    float4 bv = reinterpret_cast<const float4*>(B1)[lane];
#pragma unroll 1
    for (int rr = 0; rr < 8; rr++) {
        int r = w * 8 + rr;
        int node = row0 + r;
        float4 acc = make_float4(0.f, 0.f, 0.f, 0.f);
        if (node < M) {
            acc = *reinterpret_cast<const float4*>(&g_hs1[(size_t)node * 128 + l4]);
            int e = g_rowptr[node];
            const int e1 = g_rowptr[node + 1];
            for (; e + 1 < e1; e += 2) {
                int s0 = g_esrc[e], s1 = g_esrc[e + 1];
                float4 v0 = *reinterpret_cast<const float4*>(&g_hs1[(size_t)s0 * 128 + l4]);
                float4 v1 = *reinterpret_cast<const float4*>(&g_hs1[(size_t)s1 * 128 + l4]);
                acc.x += v0.x + v1.x;
                acc.y += v0.y + v1.y;
                acc.z += v0.z + v1.z;
                acc.w += v0.w + v1.w;
            }
            if (e < e1) {
                int s = g_esrc[e];
                float4 v = *reinterpret_cast<const float4*>(&g_hs1[(size_t)s * 128 + l4]);
                acc.x += v.x; acc.y += v.y; acc.z += v.z; acc.w += v.w;
            }
            float dv = g_dinv[node];
            acc.x = fmaxf(fmaf(dv, acc.x, bv.x), 0.f);
            acc.y = fmaxf(fmaf(dv, acc.y, bv.y), 0.f);
            acc.z = fmaxf(fmaf(dv, acc.z, bv.z), 0.f);
            acc.w = fmaxf(fmaf(dv, acc.w, bv.w), 0.f);
        }
        As[r][l4 + 0] = acc.x;
        As[r][l4 + 1] = acc.y;
        As[r][l4 + 2] = acc.z;
        As[r][l4 + 3] = acc.w;
    }

    // ---- phase 2: GEMM 64x64, thread tile 4x4 ----
    const int tx = tid & 15, ty = tid >> 4;
    const int r0 = ty * 4, c0 = tx * 4;

    float acc2[4][4];
#pragma unroll
    for (int i = 0; i < 4; i++)
#pragma unroll
        for (int j = 0; j < 4; j++) acc2[i][j] = 0.f;

    for (int kc = 0; kc < 4; kc++) {
#pragma unroll
        for (int l = 0; l < 2; l++) {
            int i = tid + l * 256;
            reinterpret_cast<float4*>(&Bs[0][0])[i] =
                reinterpret_cast<const float4*>(W2 + (size_t)kc * 32 * 64)[i];
        }
        __syncthreads();

#pragma unroll
        for (int k = 0; k < 32; k++) {
            int kk = kc * 32 + k;
            float a[4];
#pragma unroll
            for (int i = 0; i < 4; i++) a[i] = As[r0 + i][kk];
            float4 b4 = *reinterpret_cast<float4*>(&Bs[k][c0]);
            float b[4] = {b4.x, b4.y, b4.z, b4.w};
#pragma unroll
            for (int i = 0; i < 4; i++)
#pragma unroll
                for (int j = 0; j < 4; j++) acc2[i][j] = fmaf(a[i], b[j], acc2[i][j]);
        }
        __syncthreads();
    }

#pragma unroll
    for (int i = 0; i < 4; i++) {
        int gr = row0 + r0 + i;
        if (gr >= M) break;
        float dv = g_dinv[gr];
        float4 v;
        v.x = acc2[i][0] * dv;
        v.y = acc2[i][1] * dv;
        v.z = acc2[i][2] * dv;
        v.w = acc2[i][3] * dv;
        *reinterpret_cast<float4*>(&g_hs2[(size_t)gr * 64 + c0]) = v;
    }
}

// ---------------------------------------------------------------------------
// Edge aggregate 2 + final (CSR): half-warp per node, lane-half l (0..15)
// owns float4 feature slice. OUT[d] = dinv[d]*(hs2[d]+sum hs2[src]) + b2.
// ---------------------------------------------------------------------------
__global__ __launch_bounds__(256) void k_edge2(float* __restrict__ OUT,
                                               const float* __restrict__ B2,
                                               int n) {
    int gt = blockIdx.x * 256 + threadIdx.x;
    int node = gt >> 4;
    if (node >= n) return;
    int l4 = (gt & 15) * 4;

    float4 acc = *reinterpret_cast<const float4*>(&g_hs2[(size_t)node * 64 + l4]);
    int e = g_rowptr[node];
    const int e1 = g_rowptr[node + 1];
    for (; e + 1 < e1; e += 2) {
        int s0 = g_esrc[e], s1 = g_esrc[e + 1];
        float4 v0 = *reinterpret_cast<const float4*>(&g_hs2[(size_t)s0 * 64 + l4]);
        float4 v1 = *reinterpret_cast<const float4*>(&g_hs2[(size_t)s1 * 64 + l4]);
        acc.x += v0.x + v1.x;
        acc.y += v0.y + v1.y;
        acc.z += v0.z + v1.z;
        acc.w += v0.w + v1.w;
    }
    if (e < e1) {
        int s = g_esrc[e];
        float4 v = *reinterpret_cast<const float4*>(&g_hs2[(size_t)s * 64 + l4]);
        acc.x += v.x; acc.y += v.y; acc.z += v.z; acc.w += v.w;
    }

    float dv = g_dinv[node];
    float4 b = *reinterpret_cast<const float4*>(&B2[l4]);
    acc.x = fmaf(dv, acc.x, b.x);
    acc.y = fmaf(dv, acc.y, b.y);
    acc.z = fmaf(dv, acc.z, b.z);
    acc.w = fmaf(dv, acc.w, b.w);
    *reinterpret_cast<float4*>(&OUT[(size_t)node * 64 + l4]) = acc;
}

// ---------------------------------------------------------------------------
extern "C" void kernel_launch(void* const* d_in, const int* in_sizes, int n_in,
                              void* d_out, int out_size) {
    const float* x  = (const float*)d_in[0];
    const int*   ei = (const int*)d_in[1];
    const float* W1 = (const float*)d_in[2];
    const float* b1 = (const float*)d_in[3];
    const float* W2 = (const float*)d_in[4];
    const float* b2 = (const float*)d_in[5];
    float* out = (float*)d_out;

    const int N = in_sizes[0] / 128;
    const int E = in_sizes[1] / 2;
    const int* src = ei;
    const int* dst = ei + E;

    k_init<<<(N + 255) / 256, 256>>>(N);
    k_count<<<(E + 255) / 256, 256>>>(dst, E);
    k_scan<<<1, 1024>>>(N);
    k_sort<<<(E + 255) / 256, 256>>>(src, dst, E);

    k_gemm1<<<(N + 127) / 128, 256>>>(x, W1, N);
    k_fused2<<<(N + 63) / 64, 256>>>(W2, b1, N);
    {
        long long T = (long long)N * 16;
        k_edge2<<<(int)((T + 255) / 256), 256>>>(out, b2, N);
    }
}

// round 9
// speedup vs baseline: 1.1771x; 1.1771x over previous
#include <cuda_runtime.h>
#include <cstdint>

// ---------------------------------------------------------------------------
// StandGCN2: 2-layer GCN. N<=100096, F=128 -> 128 -> 64.
//   dinv = rsqrt(1+indeg)
//   hs1  = dinv[r]*(x @ W1)            (TF32 mma.sync tensor-core GEMM)
//   agg1[d] = hs1[d] + sum hs1[src]    (bucketed smem scatter, no atomics)
//   h1   = relu(dinv*agg1 + b1)        (fused into GEMM2 A-load)
//   hs2  = dinv[r]*(h1 @ W2)           (fp32 FFMA GEMM)
//   OUT[d] = dinv[d]*(hs2[d]+sum hs2[src]) + b2
// Edges counting-sorted by dst>>4 into 16-node buckets (R5 structure).
// ---------------------------------------------------------------------------

#define MAXN 100096
#define MAXB (MAXN / 16)
#define MAXE 1200000

__device__ float g_deg[MAXN];
__device__ float g_dinv[MAXN];
__device__ __align__(16) float g_hs1[(size_t)MAXN * 128];
__device__ __align__(16) float g_agg1[(size_t)MAXN * 128];
__device__ __align__(16) float g_hs2[(size_t)MAXN * 64];

__device__ int g_esrc[MAXE];
__device__ int g_edst[MAXE];
__device__ int g_bstart[MAXB + 1];
__device__ int g_bcur[MAXB];

// ---------------------------------------------------------------------------
// Preprocessing
// ---------------------------------------------------------------------------
__global__ void k_init(int n, int nb) {
    int i = blockIdx.x * blockDim.x + threadIdx.x;
    if (i < n) g_deg[i] = 1.0f;
    if (i < nb) g_bcur[i] = 0;
}

__global__ void k_count(const int* __restrict__ dst, int e) {
    int i = blockIdx.x * blockDim.x + threadIdx.x;
    if (i >= e) return;
    int d = dst[i];
    atomicAdd(&g_deg[d], 1.0f);
    atomicAdd(&g_bcur[d >> 4], 1);
}

__global__ void k_dinv(int n) {
    int i = blockIdx.x * blockDim.x + threadIdx.x;
    if (i < n) g_dinv[i] = rsqrtf(g_deg[i]);
}

// Single-block warp-shuffle exclusive scan over <=8192 bucket counts.
__global__ void k_scan(int nb) {
    __shared__ int wsum[32];
    const int t = threadIdx.x;
    const int per = (nb + 1023) / 1024;  // <= 8
    const int base = t * per;
    int v[8];
    int s = 0;
#pragma unroll
    for (int i = 0; i < 8; i++) {
        int idx = base + i;
        int x = (i < per && idx < nb) ? g_bcur[idx] : 0;
        v[i] = s;
        s += x;
    }
    const int lane = t & 31, w = t >> 5;
    int ps = s;
#pragma unroll
    for (int o = 1; o < 32; o <<= 1) {
        int y = __shfl_up_sync(0xFFFFFFFFu, ps, o);
        if (lane >= o) ps += y;
    }
    if (lane == 31) wsum[w] = ps;
    __syncthreads();
    if (w == 0) {
        int ws = wsum[lane];
#pragma unroll
        for (int o = 1; o < 32; o <<= 1) {
            int y = __shfl_up_sync(0xFFFFFFFFu, ws, o);
            if (lane >= o) ws += y;
        }
        wsum[lane] = ws;
    }
    __syncthreads();
    int excl = ps - s + (w > 0 ? wsum[w - 1] : 0);
#pragma unroll
    for (int i = 0; i < 8; i++) {
        int idx = base + i;
        if (i < per && idx < nb) {
            int e = excl + v[i];
            g_bstart[idx] = e;
            g_bcur[idx] = e;
        }
    }
    if (t == 1023) g_bstart[nb] = excl + s;
}

__global__ void k_sort(const int* __restrict__ src, const int* __restrict__ dst,
                       int e) {
    int i = blockIdx.x * blockDim.x + threadIdx.x;
    if (i >= e) return;
    int s = src[i], d = dst[i];
    int pos = atomicAdd(&g_bcur[d >> 4], 1);
    g_esrc[pos] = s;
    g_edst[pos] = d;
}

// ---------------------------------------------------------------------------
// GEMM1 (tensor core, TF32 mma.sync m16n8k8):
//   hs1 = dinv[r] * (X @ W1),  X:[M,128], W1:[128,128]
// Block: 64 rows x 128 cols, 256 threads = 8 warps (4 row-groups x 2 col-
// groups). Warp tile 16x64. Full K=128 staged once in frag-major layouts:
//   A frag (m16k8, tf32): a0=[r=l/4][k=l%4] a1=[r+8][k] a2=[r][k+4] a3=[r+8][k+4]
//   B frag (k8n8):        b0=[k=l%4][n=l/4] b1=[k+4][n]
// A smem 32KB + B smem 64KB = 96KB dynamic.
// ---------------------------------------------------------------------------
#define G1_SMEM (96 * 1024)

__device__ __forceinline__ uint32_t f2tf32(float x) {
    uint32_t u;
    asm("cvt.rna.tf32.f32 %0, %1;" : "=r"(u) : "f"(x));
    return u;
}

__global__ __launch_bounds__(256) void k_gemm1(const float* __restrict__ X,
                                               const float* __restrict__ W,
                                               int M) {
    extern __shared__ uint32_t sm[];
    uint32_t* Afr = sm;          // [(wr*16+ks)*32+lane]*4 + reg   (8192)
    uint32_t* Bfr = sm + 8192;   // [(gnt*16+ks)*32+lane]*2 + reg  (16384)

    const int tid = threadIdx.x;
    const int row0 = blockIdx.x * 64;

    // ---- stage A (64 rows x 128 k), tf32-rounded, frag-major ----
#pragma unroll
    for (int l = 0; l < 8; l++) {
        int i = tid + l * 256;       // 2048 float4
        int r = i >> 5, q4 = i & 31; // k = q4*4 + c
        int gr = row0 + r;
        float4 v = make_float4(0.f, 0.f, 0.f, 0.f);
        if (gr < M) v = reinterpret_cast<const float4*>(X)[(size_t)gr * 32 + q4];
        int wr = r >> 4, rr = r & 15;
        int ks = q4 >> 1;
        int reg = (rr >> 3) + ((q4 & 1) << 1);
        int a0 = (wr * 16 + ks) * 32 + (rr & 7) * 4;
        Afr[(a0 + 0) * 4 + reg] = f2tf32(v.x);
        Afr[(a0 + 1) * 4 + reg] = f2tf32(v.y);
        Afr[(a0 + 2) * 4 + reg] = f2tf32(v.z);
        Afr[(a0 + 3) * 4 + reg] = f2tf32(v.w);
    }
    // ---- stage B = W1 (128 k x 128 n), frag-major ----
#pragma unroll
    for (int l = 0; l < 16; l++) {
        int i = tid + l * 256;       // 4096 float4
        int k = i >> 5, q4 = i & 31; // n = q4*4 + c
        float4 v = reinterpret_cast<const float4*>(W)[(size_t)k * 32 + q4];
        int ks = k >> 3, kkl = k & 3, khi = (k >> 2) & 1;
        int gnt = q4 >> 1, nnb = (q4 & 1) * 4;
        int b0 = (gnt * 16 + ks) * 32 + kkl;
        Bfr[(b0 + (nnb + 0) * 4) * 2 + khi] = f2tf32(v.x);
        Bfr[(b0 + (nnb + 1) * 4) * 2 + khi] = f2tf32(v.y);
        Bfr[(b0 + (nnb + 2) * 4) * 2 + khi] = f2tf32(v.z);
        Bfr[(b0 + (nnb + 3) * 4) * 2 + khi] = f2tf32(v.w);
    }
    __syncthreads();

    // ---- compute: warp (wr, wc) does rows wr*16..+15, cols wc*64..+63 ----
    const int wid = tid >> 5, lane = tid & 31;
    const int wr = wid & 3, wc = wid >> 2;

    float c[8][4];
#pragma unroll
    for (int nt = 0; nt < 8; nt++)
#pragma unroll
        for (int j = 0; j < 4; j++) c[nt][j] = 0.f;

#pragma unroll
    for (int ks = 0; ks < 16; ks++) {
        uint4 a = *reinterpret_cast<const uint4*>(
            &Afr[((wr * 16 + ks) * 32 + lane) * 4]);
#pragma unroll
        for (int nt = 0; nt < 8; nt++) {
            uint2 b = *reinterpret_cast<const uint2*>(
                &Bfr[(((wc * 8 + nt) * 16 + ks) * 32 + lane) * 2]);
            asm volatile(
                "mma.sync.aligned.m16n8k8.row.col.f32.tf32.tf32.f32 "
                "{%0,%1,%2,%3}, {%4,%5,%6,%7}, {%8,%9}, {%0,%1,%2,%3};"
                : "+f"(c[nt][0]), "+f"(c[nt][1]), "+f"(c[nt][2]), "+f"(c[nt][3])
                : "r"(a.x), "r"(a.y), "r"(a.z), "r"(a.w), "r"(b.x), "r"(b.y));
        }
    }

    // ---- epilogue: scale by dinv, store to hs1 ----
    int rl = row0 + wr * 16 + (lane >> 2);
    int rh = rl + 8;
    int cb = wc * 64 + (lane & 3) * 2;
    float dl = (rl < M) ? g_dinv[rl] : 0.f;
    float dh = (rh < M) ? g_dinv[rh] : 0.f;
#pragma unroll
    for (int nt = 0; nt < 8; nt++) {
        int col = cb + nt * 8;
        if (rl < M) {
            float2 v = make_float2(c[nt][0] * dl, c[nt][1] * dl);
            *reinterpret_cast<float2*>(&g_hs1[(size_t)rl * 128 + col]) = v;
        }
        if (rh < M) {
            float2 v = make_float2(c[nt][2] * dh, c[nt][3] * dh);
            *reinterpret_cast<float2*>(&g_hs1[(size_t)rh * 128 + col]) = v;
        }
    }
}

// ---------------------------------------------------------------------------
// Edge aggregate 1: agg1[d] = hs1[d] + sum hs1[src]. Warp per 16-node bucket.
// ---------------------------------------------------------------------------
__global__ __launch_bounds__(128) void k_edge1(int n, int nb) {
    __shared__ __align__(16) float acc[4][16][128];

    const int w = threadIdx.x >> 5;
    const int l4 = (threadIdx.x & 31) * 4;
    const int b = blockIdx.x * 4 + w;
    if (b >= nb) return;
    const int n0 = b * 16;

#pragma unroll
    for (int r = 0; r < 16; r++) {
        int node = n0 + r;
        float4 v = make_float4(0.f, 0.f, 0.f, 0.f);
        if (node < n)
            v = *reinterpret_cast<const float4*>(&g_hs1[(size_t)node * 128 + l4]);
        *reinterpret_cast<float4*>(&acc[w][r][l4]) = v;
    }

    int e = g_bstart[b];
    const int e1 = g_bstart[b + 1];
    for (; e + 3 < e1; e += 4) {
        int s0 = g_esrc[e],     d0 = g_edst[e];
        int s1 = g_esrc[e + 1], d1 = g_edst[e + 1];
        int s2 = g_esrc[e + 2], d2 = g_edst[e + 2];
        int s3 = g_esrc[e + 3], d3 = g_edst[e + 3];
        float4 v0 = *reinterpret_cast<const float4*>(&g_hs1[(size_t)s0 * 128 + l4]);
        float4 v1 = *reinterpret_cast<const float4*>(&g_hs1[(size_t)s1 * 128 + l4]);
        float4 v2 = *reinterpret_cast<const float4*>(&g_hs1[(size_t)s2 * 128 + l4]);
        float4 v3 = *reinterpret_cast<const float4*>(&g_hs1[(size_t)s3 * 128 + l4]);
        float4* a;
        float4 o;
        a = reinterpret_cast<float4*>(&acc[w][d0 - n0][l4]); o = *a;
        o.x += v0.x; o.y += v0.y; o.z += v0.z; o.w += v0.w; *a = o;
        a = reinterpret_cast<float4*>(&acc[w][d1 - n0][l4]); o = *a;
        o.x += v1.x; o.y += v1.y; o.z += v1.z; o.w += v1.w; *a = o;
        a = reinterpret_cast<float4*>(&acc[w][d2 - n0][l4]); o = *a;
        o.x += v2.x; o.y += v2.y; o.z += v2.z; o.w += v2.w; *a = o;
        a = reinterpret_cast<float4*>(&acc[w][d3 - n0][l4]); o = *a;
        o.x += v3.x; o.y += v3.y; o.z += v3.z; o.w += v3.w; *a = o;
    }
    for (; e < e1; e++) {
        int s = g_esrc[e], d = g_edst[e];
        float4 v = *reinterpret_cast<const float4*>(&g_hs1[(size_t)s * 128 + l4]);
        float4* a = reinterpret_cast<float4*>(&acc[w][d - n0][l4]);
        float4 o = *a;
        o.x += v.x; o.y += v.y; o.z += v.z; o.w += v.w;
        *a = o;
    }

#pragma unroll
    for (int r = 0; r < 16; r++) {
        int node = n0 + r;
        if (node < n)
            *reinterpret_cast<float4*>(&g_agg1[(size_t)node * 128 + l4]) =
                *reinterpret_cast<const float4*>(&acc[w][r][l4]);
    }
}

// ---------------------------------------------------------------------------
// GEMM2 (fp32 FFMA): A[r][k] = relu(dinv[r]*agg1[r][k] + b1[k]) fused on load;
// hs2 = dinv[r]*(A @ W2). Block 64x64, thread tile 4x4 (proven R3/R5 version).
// ---------------------------------------------------------------------------
__global__ __launch_bounds__(256) void k_gemm2(const float* __restrict__ W2,
                                               const float* __restrict__ B1,
                                               int M) {
    __shared__ float As[64][33];
    __shared__ float Bs[32][64];

    const int tid = threadIdx.x;
    const int row0 = blockIdx.x * 64;
    const int tx = tid & 15, ty = tid >> 4;
    const int r0 = ty * 4, c0 = tx * 4;

    float acc[4][4];
#pragma unroll
    for (int i = 0; i < 4; i++)
#pragma unroll
        for (int j = 0; j < 4; j++) acc[i][j] = 0.f;

    for (int kc = 0; kc < 4; kc++) {
#pragma unroll
        for (int l = 0; l < 2; l++) {
            int i = tid + l * 256;
            int r = i >> 3, q = i & 7;
            int gr = row0 + r;
            float4 v = make_float4(0.f, 0.f, 0.f, 0.f);
            if (gr < M) {
                v = reinterpret_cast<const float4*>(g_agg1)[(size_t)gr * 32 + kc * 8 + q];
                float dv = g_dinv[gr];
                int kb = kc * 32 + q * 4;
                v.x = fmaxf(fmaf(dv, v.x, B1[kb + 0]), 0.f);
                v.y = fmaxf(fmaf(dv, v.y, B1[kb + 1]), 0.f);
                v.z = fmaxf(fmaf(dv, v.z, B1[kb + 2]), 0.f);
                v.w = fmaxf(fmaf(dv, v.w, B1[kb + 3]), 0.f);
            }
            As[r][q * 4 + 0] = v.x;
            As[r][q * 4 + 1] = v.y;
            As[r][q * 4 + 2] = v.z;
            As[r][q * 4 + 3] = v.w;
        }
#pragma unroll
        for (int l = 0; l < 2; l++) {
            int i = tid + l * 256;
            reinterpret_cast<float4*>(&Bs[0][0])[i] =
                reinterpret_cast<const float4*>(W2 + (size_t)kc * 32 * 64)[i];
        }
        __syncthreads();

#pragma unroll
        for (int k = 0; k < 32; k++) {
            float a[4];
#pragma unroll
            for (int i = 0; i < 4; i++) a[i] = As[r0 + i][k];
            float4 b4 = *reinterpret_cast<float4*>(&Bs[k][c0]);
            float b[4] = {b4.x, b4.y, b4.z, b4.w};
#pragma unroll
            for (int i = 0; i < 4; i++)
#pragma unroll
                for (int j = 0; j < 4; j++) acc[i][j] = fmaf(a[i], b[j], acc[i][j]);
        }
        __syncthreads();
    }

#pragma unroll
    for (int i = 0; i < 4; i++) {
        int gr = row0 + r0 + i;
        if (gr >= M) break;
        float dv = g_dinv[gr];
        float4 v;
        v.x = acc[i][0] * dv;
        v.y = acc[i][1] * dv;
        v.z = acc[i][2] * dv;
        v.w = acc[i][3] * dv;
        *reinterpret_cast<float4*>(&g_hs2[(size_t)gr * 64 + c0]) = v;
    }
}

// ---------------------------------------------------------------------------
// Edge aggregate 2 + final: OUT[d] = dinv[d]*(hs2[d]+sum hs2[src]) + b2
// ---------------------------------------------------------------------------
__global__ __launch_bounds__(128) void k_edge2(float* __restrict__ OUT,
                                               const float* __restrict__ B2,
                                               int n, int nb) {
    __shared__ __align__(8) float acc[4][16][64];

    const int w = threadIdx.x >> 5;
    const int l2 = (threadIdx.x & 31) * 2;
    const int b = blockIdx.x * 4 + w;
    if (b >= nb) return;
    const int n0 = b * 16;

#pragma unroll
    for (int r = 0; r < 16; r++) {
        int node = n0 + r;
        float2 v = make_float2(0.f, 0.f);
        if (node < n)
            v = *reinterpret_cast<const float2*>(&g_hs2[(size_t)node * 64 + l2]);
        *reinterpret_cast<float2*>(&acc[w][r][l2]) = v;
    }

    int e = g_bstart[b];
    const int e1 = g_bstart[b + 1];
    for (; e + 3 < e1; e += 4) {
        int s0 = g_esrc[e],     d0 = g_edst[e];
        int s1 = g_esrc[e + 1], d1 = g_edst[e + 1];
        int s2 = g_esrc[e + 2], d2 = g_edst[e + 2];
        int s3 = g_esrc[e + 3], d3 = g_edst[e + 3];
        float2 v0 = *reinterpret_cast<const float2*>(&g_hs2[(size_t)s0 * 64 + l2]);
        float2 v1 = *reinterpret_cast<const float2*>(&g_hs2[(size_t)s1 * 64 + l2]);
        float2 v2 = *reinterpret_cast<const float2*>(&g_hs2[(size_t)s2 * 64 + l2]);
        float2 v3 = *reinterpret_cast<const float2*>(&g_hs2[(size_t)s3 * 64 + l2]);
        float2* a;
        float2 o;
        a = reinterpret_cast<float2*>(&acc[w][d0 - n0][l2]); o = *a;
        o.x += v0.x; o.y += v0.y; *a = o;
        a = reinterpret_cast<float2*>(&acc[w][d1 - n0][l2]); o = *a;
        o.x += v1.x; o.y += v1.y; *a = o;
        a = reinterpret_cast<float2*>(&acc[w][d2 - n0][l2]); o = *a;
        o.x += v2.x; o.y += v2.y; *a = o;
        a = reinterpret_cast<float2*>(&acc[w][d3 - n0][l2]); o = *a;
        o.x += v3.x; o.y += v3.y; *a = o;
    }
    for (; e < e1; e++) {
        int s = g_esrc[e], d = g_edst[e];
        float2 v = *reinterpret_cast<const float2*>(&g_hs2[(size_t)s * 64 + l2]);
        float2* a = reinterpret_cast<float2*>(&acc[w][d - n0][l2]);
        float2 o = *a;
        o.x += v.x; o.y += v.y;
        *a = o;
    }

    float2 bb = *reinterpret_cast<const float2*>(&B2[l2]);
#pragma unroll
    for (int r = 0; r < 16; r++) {
        int node = n0 + r;
        if (node < n) {
            float dv = g_dinv[node];
            float2 o = *reinterpret_cast<const float2*>(&acc[w][r][l2]);
            o.x = fmaf(dv, o.x, bb.x);
            o.y = fmaf(dv, o.y, bb.y);
            *reinterpret_cast<float2*>(&OUT[(size_t)node * 64 + l2]) = o;
        }
    }
}

// ---------------------------------------------------------------------------
extern "C" void kernel_launch(void* const* d_in, const int* in_sizes, int n_in,
                              void* d_out, int out_size) {
    const float* x  = (const float*)d_in[0];
    const int*   ei = (const int*)d_in[1];
    const float* W1 = (const float*)d_in[2];
    const float* b1 = (const float*)d_in[3];
    const float* W2 = (const float*)d_in[4];
    const float* b2 = (const float*)d_in[5];
    float* out = (float*)d_out;

    const int N = in_sizes[0] / 128;
    const int E = in_sizes[1] / 2;
    const int NB = (N + 15) / 16;
    const int* src = ei;
    const int* dst = ei + E;

    static bool attr_set = false;
    if (!attr_set) {
        cudaFuncSetAttribute(k_gemm1, cudaFuncAttributeMaxDynamicSharedMemorySize,
                             G1_SMEM);
        attr_set = true;
    }

    int mx = (N > NB) ? N : NB;
    k_init<<<(mx + 255) / 256, 256>>>(N, NB);
    k_count<<<(E + 255) / 256, 256>>>(dst, E);
    k_dinv<<<(N + 255) / 256, 256>>>(N);
    k_scan<<<1, 1024>>>(NB);
    k_sort<<<(E + 255) / 256, 256>>>(src, dst, E);

    k_gemm1<<<(N + 63) / 64, 256, G1_SMEM>>>(x, W1, N);
    k_edge1<<<(NB + 3) / 4, 128>>>(N, NB);
    k_gemm2<<<(N + 63) / 64, 256>>>(W2, b1, N);
    k_edge2<<<(NB + 3) / 4, 128>>>(out, b2, N, NB);
}

// round 10
// speedup vs baseline: 1.5467x; 1.3140x over previous
#include <cuda_runtime.h>
#include <cstdint>

// ---------------------------------------------------------------------------
// StandGCN2: 2-layer GCN. N<=100096, F=128 -> 128 -> 64.
//   dinv = rsqrt(1+indeg)
//   hs1  = x @ W1                      (GEMM1, f32x2 packed FMA, NO dinv --
//                                       makes GEMM1 independent of preproc)
//   agg1[d] = dinv[d]*hs1[d] + sum dinv[s]*hs1[s]   (bucketed smem scatter)
//   h1   = relu(dinv*agg1 + b1)        (fused into GEMM2 A-load)
//   hs2  = dinv[r]*(h1 @ W2)           (GEMM2 fp32)
//   OUT[d] = dinv[d]*(hs2[d]+sum hs2[src]) + b2
// Preprocessing (degree/scan/sort) runs on a forked side stream, overlapped
// with GEMM1; joined via event before edge1.
// ---------------------------------------------------------------------------

#define MAXN 100096
#define MAXB (MAXN / 16)
#define MAXE 1200000

__device__ float g_deg[MAXN];
__device__ float g_dinv[MAXN];
__device__ __align__(16) float g_hs1[(size_t)MAXN * 128];
__device__ __align__(16) float g_agg1[(size_t)MAXN * 128];
__device__ __align__(16) float g_hs2[(size_t)MAXN * 64];

__device__ int g_esrc[MAXE];
__device__ int g_edst[MAXE];
__device__ int g_bstart[MAXB + 1];
__device__ int g_bcur[MAXB];

typedef unsigned long long u64;

#define FMA2(d, a, b) \
    asm("fma.rn.f32x2 %0, %1, %2, %3;" : "=l"(d) : "l"(a), "l"(b), "l"(d))
#define DUP2(d, x) \
    asm("mov.b64 %0, {%1, %1};" : "=l"(d) : "r"(__float_as_uint(x)))

__device__ __forceinline__ float2 u64_as_f2(u64 v) {
    float2 r;
    asm("mov.b64 {%0, %1}, %2;" : "=f"(r.x), "=f"(r.y) : "l"(v));
    return r;
}

// ---------------------------------------------------------------------------
// Preprocessing (side stream)
// ---------------------------------------------------------------------------
__global__ void k_init(int n, int nb) {
    int i = blockIdx.x * blockDim.x + threadIdx.x;
    if (i < n) g_deg[i] = 1.0f;
    if (i < nb) g_bcur[i] = 0;
}

__global__ void k_count(const int* __restrict__ dst, int e) {
    int i = blockIdx.x * blockDim.x + threadIdx.x;
    if (i >= e) return;
    int d = dst[i];
    atomicAdd(&g_deg[d], 1.0f);
    atomicAdd(&g_bcur[d >> 4], 1);
}

__global__ void k_dinv(int n) {
    int i = blockIdx.x * blockDim.x + threadIdx.x;
    if (i < n) g_dinv[i] = rsqrtf(g_deg[i]);
}

// Single-block warp-shuffle exclusive scan over <=8192 bucket counts.
__global__ void k_scan(int nb) {
    __shared__ int wsum[32];
    const int t = threadIdx.x;
    const int per = (nb + 1023) / 1024;  // <= 8
    const int base = t * per;
    int v[8];
    int s = 0;
#pragma unroll
    for (int i = 0; i < 8; i++) {
        int idx = base + i;
        int x = (i < per && idx < nb) ? g_bcur[idx] : 0;
        v[i] = s;
        s += x;
    }
    const int lane = t & 31, w = t >> 5;
    int ps = s;
#pragma unroll
    for (int o = 1; o < 32; o <<= 1) {
        int y = __shfl_up_sync(0xFFFFFFFFu, ps, o);
        if (lane >= o) ps += y;
    }
    if (lane == 31) wsum[w] = ps;
    __syncthreads();
    if (w == 0) {
        int ws = wsum[lane];
#pragma unroll
        for (int o = 1; o < 32; o <<= 1) {
            int y = __shfl_up_sync(0xFFFFFFFFu, ws, o);
            if (lane >= o) ws += y;
        }
        wsum[lane] = ws;
    }
    __syncthreads();
    int excl = ps - s + (w > 0 ? wsum[w - 1] : 0);
#pragma unroll
    for (int i = 0; i < 8; i++) {
        int idx = base + i;
        if (i < per && idx < nb) {
            int e = excl + v[i];
            g_bstart[idx] = e;
            g_bcur[idx] = e;
        }
    }
    if (t == 1023) g_bstart[nb] = excl + s;
}

__global__ void k_sort(const int* __restrict__ src, const int* __restrict__ dst,
                       int e) {
    int i = blockIdx.x * blockDim.x + threadIdx.x;
    if (i >= e) return;
    int s = src[i], d = dst[i];
    int pos = atomicAdd(&g_bcur[d >> 4], 1);
    g_esrc[pos] = s;
    g_edst[pos] = d;
}

// ---------------------------------------------------------------------------
// GEMM1: hs1 = X @ W1 (raw, no dinv),  X:[M,128], W1:[128,128]
// Block 128x128, 256 threads, 8x8 microtile via f32x2, double-buffered.
// ---------------------------------------------------------------------------
__global__ __launch_bounds__(256, 2) void k_gemm1(const float* __restrict__ X,
                                                  const float* __restrict__ W,
                                                  int M) {
    __shared__ float As[2][16][128];
    __shared__ float Bs[2][16][128];

    const int tid = threadIdx.x;
    const int row0 = blockIdx.x * 128;
    const int tx = tid & 15, ty = tid >> 4;
    const int r0 = ty * 8, c0 = tx * 8;

    u64 acc[4][8];
#pragma unroll
    for (int i = 0; i < 4; i++)
#pragma unroll
        for (int j = 0; j < 8; j++) acc[i][j] = 0ull;

    float4 ra[2], rb[2];

    auto ldg = [&](int kc) {
#pragma unroll
        for (int l = 0; l < 2; l++) {
            int i = tid + l * 256;
            int r = i & 127, q4 = i >> 7;
            int gr = row0 + r;
            ra[l] = make_float4(0.f, 0.f, 0.f, 0.f);
            if (gr < M)
                ra[l] = reinterpret_cast<const float4*>(X)[(size_t)gr * 32 + kc * 4 + q4];
            rb[l] = reinterpret_cast<const float4*>(W)[(size_t)kc * 512 + i];
        }
    };
    auto sts = [&](int buf) {
#pragma unroll
        for (int l = 0; l < 2; l++) {
            int i = tid + l * 256;
            int r = i & 127, q4 = i >> 7;
            As[buf][q4 * 4 + 0][r] = ra[l].x;
            As[buf][q4 * 4 + 1][r] = ra[l].y;
            As[buf][q4 * 4 + 2][r] = ra[l].z;
            As[buf][q4 * 4 + 3][r] = ra[l].w;
            reinterpret_cast<float4*>(&Bs[buf][0][0])[i] = rb[l];
        }
    };

    ldg(0);
    sts(0);
    ldg(1);
    __syncthreads();

    for (int kc = 0; kc < 8; kc++) {
        const int cur = kc & 1;
        if (kc + 1 < 8) sts((kc + 1) & 1);
        if (kc + 2 < 8) ldg(kc + 2);
#pragma unroll
        for (int k = 0; k < 16; k++) {
            ulonglong2 a01 = *reinterpret_cast<const ulonglong2*>(&As[cur][k][r0]);
            ulonglong2 a23 = *reinterpret_cast<const ulonglong2*>(&As[cur][k][r0 + 4]);
            float4 bl = *reinterpret_cast<const float4*>(&Bs[cur][k][c0]);
            float4 bh = *reinterpret_cast<const float4*>(&Bs[cur][k][c0 + 4]);
            u64 ap[4] = {a01.x, a01.y, a23.x, a23.y};
            u64 bb[8];
            DUP2(bb[0], bl.x); DUP2(bb[1], bl.y); DUP2(bb[2], bl.z); DUP2(bb[3], bl.w);
            DUP2(bb[4], bh.x); DUP2(bb[5], bh.y); DUP2(bb[6], bh.z); DUP2(bb[7], bh.w);
#pragma unroll
            for (int rp = 0; rp < 4; rp++)
#pragma unroll
                for (int j = 0; j < 8; j++) FMA2(acc[rp][j], ap[rp], bb[j]);
        }
        __syncthreads();
    }

#pragma unroll
    for (int rp = 0; rp < 4; rp++) {
        int gre = row0 + r0 + 2 * rp;
        float2 p[8];
#pragma unroll
        for (int j = 0; j < 8; j++) p[j] = u64_as_f2(acc[rp][j]);
#pragma unroll
        for (int h = 0; h < 2; h++) {
            int gr = gre + h;
            if (gr >= M) break;
            float4 v0, v1;
            if (h == 0) {
                v0 = make_float4(p[0].x, p[1].x, p[2].x, p[3].x);
                v1 = make_float4(p[4].x, p[5].x, p[6].x, p[7].x);
            } else {
                v0 = make_float4(p[0].y, p[1].y, p[2].y, p[3].y);
                v1 = make_float4(p[4].y, p[5].y, p[6].y, p[7].y);
            }
            *reinterpret_cast<float4*>(&g_hs1[(size_t)gr * 128 + c0]) = v0;
            *reinterpret_cast<float4*>(&g_hs1[(size_t)gr * 128 + c0 + 4]) = v1;
        }
    }
}

// ---------------------------------------------------------------------------
// Edge aggregate 1: agg1[d] = dinv[d]*hs1[d] + sum dinv[s]*hs1[s].
// Warp per 16-node bucket, 8-wide unrolled gather for MLP.
// ---------------------------------------------------------------------------
__global__ __launch_bounds__(128) void k_edge1(int n, int nb) {
    __shared__ __align__(16) float acc[4][16][128];

    const int w = threadIdx.x >> 5;
    const int l4 = (threadIdx.x & 31) * 4;
    const int b = blockIdx.x * 4 + w;
    if (b >= nb) return;
    const int n0 = b * 16;

#pragma unroll
    for (int r = 0; r < 16; r++) {
        int node = n0 + r;
        float4 v = make_float4(0.f, 0.f, 0.f, 0.f);
        if (node < n) {
            v = *reinterpret_cast<const float4*>(&g_hs1[(size_t)node * 128 + l4]);
            float dv = g_dinv[node];
            v.x *= dv; v.y *= dv; v.z *= dv; v.w *= dv;
        }
        *reinterpret_cast<float4*>(&acc[w][r][l4]) = v;
    }

    int e = g_bstart[b];
    const int e1 = g_bstart[b + 1];
    for (; e + 7 < e1; e += 8) {
        int ss[8], dd[8];
#pragma unroll
        for (int j = 0; j < 8; j++) {
            ss[j] = g_esrc[e + j];
            dd[j] = g_edst[e + j];
        }
        float4 vv[8];
        float dv[8];
#pragma unroll
        for (int j = 0; j < 8; j++) {
            vv[j] = *reinterpret_cast<const float4*>(&g_hs1[(size_t)ss[j] * 128 + l4]);
            dv[j] = g_dinv[ss[j]];
        }
#pragma unroll
        for (int j = 0; j < 8; j++) {
            float4* a = reinterpret_cast<float4*>(&acc[w][dd[j] - n0][l4]);
            float4 o = *a;
            o.x = fmaf(dv[j], vv[j].x, o.x);
            o.y = fmaf(dv[j], vv[j].y, o.y);
            o.z = fmaf(dv[j], vv[j].z, o.z);
            o.w = fmaf(dv[j], vv[j].w, o.w);
            *a = o;
        }
    }
    for (; e < e1; e++) {
        int s = g_esrc[e], d = g_edst[e];
        float4 v = *reinterpret_cast<const float4*>(&g_hs1[(size_t)s * 128 + l4]);
        float dv = g_dinv[s];
        float4* a = reinterpret_cast<float4*>(&acc[w][d - n0][l4]);
        float4 o = *a;
        o.x = fmaf(dv, v.x, o.x);
        o.y = fmaf(dv, v.y, o.y);
        o.z = fmaf(dv, v.z, o.z);
        o.w = fmaf(dv, v.w, o.w);
        *a = o;
    }

#pragma unroll
    for (int r = 0; r < 16; r++) {
        int node = n0 + r;
        if (node < n)
            *reinterpret_cast<float4*>(&g_agg1[(size_t)node * 128 + l4]) =
                *reinterpret_cast<const float4*>(&acc[w][r][l4]);
    }
}

// ---------------------------------------------------------------------------
// GEMM2 (fp32): A[r][k] = relu(dinv[r]*agg1[r][k] + b1[k]) fused on load;
// hs2 = dinv[r]*(A @ W2). Block 64x64, thread tile 4x4 (proven R5 version).
// ---------------------------------------------------------------------------
__global__ __launch_bounds__(256) void k_gemm2(const float* __restrict__ W2,
                                               const float* __restrict__ B1,
                                               int M) {
    __shared__ float As[64][33];
    __shared__ float Bs[32][64];

    const int tid = threadIdx.x;
    const int row0 = blockIdx.x * 64;
    const int tx = tid & 15, ty = tid >> 4;
    const int r0 = ty * 4, c0 = tx * 4;

    float acc[4][4];
#pragma unroll
    for (int i = 0; i < 4; i++)
#pragma unroll
        for (int j = 0; j < 4; j++) acc[i][j] = 0.f;

    for (int kc = 0; kc < 4; kc++) {
#pragma unroll
        for (int l = 0; l < 2; l++) {
            int i = tid + l * 256;
            int r = i >> 3, q = i & 7;
            int gr = row0 + r;
            float4 v = make_float4(0.f, 0.f, 0.f, 0.f);
            if (gr < M) {
                v = reinterpret_cast<const float4*>(g_agg1)[(size_t)gr * 32 + kc * 8 + q];
                float dv = g_dinv[gr];
                int kb = kc * 32 + q * 4;
                v.x = fmaxf(fmaf(dv, v.x, B1[kb + 0]), 0.f);
                v.y = fmaxf(fmaf(dv, v.y, B1[kb + 1]), 0.f);
                v.z = fmaxf(fmaf(dv, v.z, B1[kb + 2]), 0.f);
                v.w = fmaxf(fmaf(dv, v.w, B1[kb + 3]), 0.f);
            }
            As[r][q * 4 + 0] = v.x;
            As[r][q * 4 + 1] = v.y;
            As[r][q * 4 + 2] = v.z;
            As[r][q * 4 + 3] = v.w;
        }
#pragma unroll
        for (int l = 0; l < 2; l++) {
            int i = tid + l * 256;
            reinterpret_cast<float4*>(&Bs[0][0])[i] =
                reinterpret_cast<const float4*>(W2 + (size_t)kc * 32 * 64)[i];
        }
        __syncthreads();

#pragma unroll
        for (int k = 0; k < 32; k++) {
            float a[4];
#pragma unroll
            for (int i = 0; i < 4; i++) a[i] = As[r0 + i][k];
            float4 b4 = *reinterpret_cast<float4*>(&Bs[k][c0]);
            float b[4] = {b4.x, b4.y, b4.z, b4.w};
#pragma unroll
            for (int i = 0; i < 4; i++)
#pragma unroll
                for (int j = 0; j < 4; j++) acc[i][j] = fmaf(a[i], b[j], acc[i][j]);
        }
        __syncthreads();
    }

#pragma unroll
    for (int i = 0; i < 4; i++) {
        int gr = row0 + r0 + i;
        if (gr >= M) break;
        float dv = g_dinv[gr];
        float4 v;
        v.x = acc[i][0] * dv;
        v.y = acc[i][1] * dv;
        v.z = acc[i][2] * dv;
        v.w = acc[i][3] * dv;
        *reinterpret_cast<float4*>(&g_hs2[(size_t)gr * 64 + c0]) = v;
    }
}

// ---------------------------------------------------------------------------
// Edge aggregate 2 + final: OUT[d] = dinv[d]*(hs2[d]+sum hs2[src]) + b2.
// Warp per 16-node bucket, 8-wide unrolled gather.
// ---------------------------------------------------------------------------
__global__ __launch_bounds__(128) void k_edge2(float* __restrict__ OUT,
                                               const float* __restrict__ B2,
                                               int n, int nb) {
    __shared__ __align__(8) float acc[4][16][64];

    const int w = threadIdx.x >> 5;
    const int l2 = (threadIdx.x & 31) * 2;
    const int b = blockIdx.x * 4 + w;
    if (b >= nb) return;
    const int n0 = b * 16;

#pragma unroll
    for (int r = 0; r < 16; r++) {
        int node = n0 + r;
        float2 v = make_float2(0.f, 0.f);
        if (node < n)
            v = *reinterpret_cast<const float2*>(&g_hs2[(size_t)node * 64 + l2]);
        *reinterpret_cast<float2*>(&acc[w][r][l2]) = v;
    }

    int e = g_bstart[b];
    const int e1 = g_bstart[b + 1];
    for (; e + 7 < e1; e += 8) {
        int ss[8], dd[8];
#pragma unroll
        for (int j = 0; j < 8; j++) {
            ss[j] = g_esrc[e + j];
            dd[j] = g_edst[e + j];
        }
        float2 vv[8];
#pragma unroll
        for (int j = 0; j < 8; j++)
            vv[j] = *reinterpret_cast<const float2*>(&g_hs2[(size_t)ss[j] * 64 + l2]);
#pragma unroll
        for (int j = 0; j < 8; j++) {
            float2* a = reinterpret_cast<float2*>(&acc[w][dd[j] - n0][l2]);
            float2 o = *a;
            o.x += vv[j].x;
            o.y += vv[j].y;
            *a = o;
        }
    }
    for (; e < e1; e++) {
        int s = g_esrc[e], d = g_edst[e];
        float2 v = *reinterpret_cast<const float2*>(&g_hs2[(size_t)s * 64 + l2]);
        float2* a = reinterpret_cast<float2*>(&acc[w][d - n0][l2]);
        float2 o = *a;
        o.x += v.x;
        o.y += v.y;
        *a = o;
    }

    float2 bb = *reinterpret_cast<const float2*>(&B2[l2]);
#pragma unroll
    for (int r = 0; r < 16; r++) {
        int node = n0 + r;
        if (node < n) {
            float dv = g_dinv[node];
            float2 o = *reinterpret_cast<const float2*>(&acc[w][r][l2]);
            o.x = fmaf(dv, o.x, bb.x);
            o.y = fmaf(dv, o.y, bb.y);
            *reinterpret_cast<float2*>(&OUT[(size_t)node * 64 + l2]) = o;
        }
    }
}

// ---------------------------------------------------------------------------
extern "C" void kernel_launch(void* const* d_in, const int* in_sizes, int n_in,
                              void* d_out, int out_size) {
    const float* x  = (const float*)d_in[0];
    const int*   ei = (const int*)d_in[1];
    const float* W1 = (const float*)d_in[2];
    const float* b1 = (const float*)d_in[3];
    const float* W2 = (const float*)d_in[4];
    const float* b2 = (const float*)d_in[5];
    float* out = (float*)d_out;

    const int N = in_sizes[0] / 128;
    const int E = in_sizes[1] / 2;
    const int NB = (N + 15) / 16;
    const int* src = ei;
    const int* dst = ei + E;

    static cudaStream_t side = nullptr;
    static cudaEvent_t evA = nullptr, evB = nullptr;
    if (!side) {
        cudaStreamCreateWithFlags(&side, cudaStreamNonBlocking);
        cudaEventCreateWithFlags(&evA, cudaEventDisableTiming);
        cudaEventCreateWithFlags(&evB, cudaEventDisableTiming);
    }

    // Fork: preprocessing on side stream, GEMM1 (independent) on main stream.
    cudaEventRecord(evA, 0);
    cudaStreamWaitEvent(side, evA, 0);

    int mx = (N > NB) ? N : NB;
    k_init<<<(mx + 255) / 256, 256, 0, side>>>(N, NB);
    k_count<<<(E + 255) / 256, 256, 0, side>>>(dst, E);
    k_dinv<<<(N + 255) / 256, 256, 0, side>>>(N);
    k_scan<<<1, 1024, 0, side>>>(NB);
    k_sort<<<(E + 255) / 256, 256, 0, side>>>(src, dst, E);
    cudaEventRecord(evB, side);

    k_gemm1<<<(N + 127) / 128, 256>>>(x, W1, N);

    // Join: edge1 needs both GEMM1 output and sorted edges + dinv.
    cudaStreamWaitEvent(0, evB, 0);

    k_edge1<<<(NB + 3) / 4, 128>>>(N, NB);
    k_gemm2<<<(N + 63) / 64, 256>>>(W2, b1, N);
    k_edge2<<<(NB + 3) / 4, 128>>>(out, b2, N, NB);
}